// round 17
// baseline (speedup 1.0000x reference)
#include <cuda_runtime.h>
#include <cuda_fp16.h>
#include <stdint.h>
#include <math.h>

// out[i] = F(x[i]) for a fixed smooth scalar F (weights shared across elems).
// Two kernels:
//   K1: warp-per-entry exact tabulation of F on [-6.5, 6.5], 1024 nodes,
//       half2 pairs {F[j], F[j+1]}; 128 blocks x 8 warps = ONE wave.
//   K2: blocked VPT=4 linear interpolation, 128-thread blocks; table held in
//       smem with 4-WAY INTERLEAVED REPLICATION (lane%4 picks the copy, so
//       the four lane-classes hit disjoint bank sets -> fewer LDS conflicts).

#define HH 20
#define GG 80
#define LN_EPS 1e-5f

#define TAB_N 1024
#define TAB_XMIN (-6.5f)
#define TAB_XMAX (6.5f)
#define TAB_STEP ((TAB_XMAX - TAB_XMIN) / (float)(TAB_N - 1))
#define TAB_INV_STEP ((float)(TAB_N - 1) / (TAB_XMAX - TAB_XMIN))
#define TAB_T_OFF (-(TAB_XMIN) * TAB_INV_STEP)
#define TAB_T_MAX ((float)(TAB_N - 1) - 0.001f)
// normalized clamp: t = saturate(x*TAB_A + TAB_B) * TAB_T_MAX
#define TAB_A (TAB_INV_STEP / TAB_T_MAX)
#define TAB_B (TAB_T_OFF / TAB_T_MAX)

__device__ __half2 g_tab_h2[TAB_N];   // {F[j], F[j+1]}

struct Weights {
    const float *W1, *b1, *g1, *be1;
    const float *Wih0, *gi0, *bi0, *bh0, *go0, *bo0;
    const float *Wih1, *gi1, *bi1, *bh1, *go1, *bo1;
    const float *Wout, *bout;
};

__device__ __forceinline__ float fast_sigmoid(float z) {
    return 1.0f / (1.0f + __expf(-z));
}
__device__ __forceinline__ float fast_tanh(float z) {
    return 1.0f - 2.0f / (1.0f + __expf(2.0f * z));
}
__device__ __forceinline__ float warp_sum(float v) {
#pragma unroll
    for (int off = 16; off; off >>= 1) v += __shfl_xor_sync(0xffffffffu, v, off);
    return v;
}

// ===================== kernel 1: warp-per-entry table build =================
#define BUILD_WARPS 8          // 1024/8 = 128 blocks = one wave on 148 SMs
#define WPITCH 21
#define WROWS  96

__device__ __forceinline__ float cell_warp(const float* __restrict__ v,
                                           const float* __restrict__ Wsm,
                                           const float* gi, const float* bi,
                                           const float* bh, const float* go,
                                           const float* bo, float* gbuf,
                                           int lane) {
    const bool v2 = lane < 16;
    const bool act = lane < HH;
    const float* w0 = Wsm + lane * WPITCH;
    const float* w1 = Wsm + (32 + lane) * WPITCH;
    const float* w2 = Wsm + (64 + lane) * WPITCH;  // rows >= 80 are zero
    float a0 = 0.f, a1 = 0.f, a2 = 0.f;
#pragma unroll
    for (int k = 0; k < HH; k++) {
        a0 = fmaf(v[k], w0[k], a0);
        a1 = fmaf(v[k], w1[k], a1);
        a2 = fmaf(v[k], w2[k], a2);
    }
    float mu = warp_sum(a0 + a1 + a2) * (1.f / 80.f);
    float d0 = a0 - mu, d1 = a1 - mu, d2 = v2 ? (a2 - mu) : 0.f;
    float var = warp_sum(fmaf(d0, d0, fmaf(d1, d1, d2 * d2))) * (1.f / 79.f);
    float inv = 1.f / (sqrtf(var) + LN_EPS);
    gbuf[lane]      = d0 * inv * gi[lane]      + bi[lane]      + bh[lane];
    gbuf[32 + lane] = d1 * inv * gi[32 + lane] + bi[32 + lane] + bh[32 + lane];
    if (v2)
        gbuf[64 + lane] = d2 * inv * gi[64 + lane] + bi[64 + lane] + bh[64 + lane];
    __syncwarp();
    float c = 0.f, ov = 0.f;
    if (act) {
        float iv = gbuf[lane];
        ov = gbuf[40 + lane];
        float gv = gbuf[60 + lane];
        c = fast_sigmoid(iv) * fast_tanh(gv);
    }
    __syncwarp();
    float mu2 = warp_sum(c) * (1.f / 20.f);
    float dc = act ? (c - mu2) : 0.f;
    float var2 = warp_sum(dc * dc) * (1.f / 19.f);
    float inv2 = 1.f / (sqrtf(var2) + LN_EPS);
    float h = 0.f;
    if (act) {
        float cn = dc * inv2 * go[lane] + bo[lane];
        h = fast_sigmoid(ov) * fast_tanh(cn);
    }
    return h;
}

__global__ void __launch_bounds__(32 * BUILD_WARPS)
build_table_kernel(Weights w) {
    __shared__ float Wih0_s[WROWS * WPITCH];
    __shared__ float Wih1_s[WROWS * WPITCH];
    __shared__ float gates_s[BUILD_WARPS][GG];
    __shared__ float hx_s[BUILD_WARPS][HH];

    int tid = threadIdx.x;
    for (int idx = tid; idx < WROWS * WPITCH; idx += blockDim.x) {
        int r = idx / WPITCH, k = idx - r * WPITCH;
        float v0 = 0.f, v1 = 0.f;
        if (r < GG && k < HH) { v0 = w.Wih0[r * HH + k]; v1 = w.Wih1[r * HH + k]; }
        Wih0_s[idx] = v0;
        Wih1_s[idx] = v1;
    }
    __syncthreads();

    int warp = tid >> 5, lane = tid & 31;
    int entry = blockIdx.x * BUILD_WARPS + warp;
    float x = fmaf((float)entry, TAB_STEP, TAB_XMIN);
    const bool act = lane < HH;

    // layer 1
    float hval = 0.f;
    if (act) hval = fmaf(x, w.W1[lane], w.b1[lane]);
    {
        float mu = warp_sum(act ? hval : 0.f) * (1.f / 20.f);
        float d = act ? (hval - mu) : 0.f;
        float var = warp_sum(d * d) * (1.f / 19.f);
        float inv = 1.f / (sqrtf(var) + LN_EPS);
        if (act) hval = fast_tanh(d * inv * w.g1[lane] + w.be1[lane]);
    }

    float v[HH];
    if (act) hx_s[warp][lane] = hval;
    __syncwarp();
#pragma unroll
    for (int k = 0; k < HH; k++) v[k] = hx_s[warp][k];
    __syncwarp();

    hval = cell_warp(v, Wih0_s, w.gi0, w.bi0, w.bh0, w.go0, w.bo0,
                     gates_s[warp], lane);

    if (act) hx_s[warp][lane] = hval;
    __syncwarp();
#pragma unroll
    for (int k = 0; k < HH; k++) v[k] = hx_s[warp][k];
    __syncwarp();

    hval = cell_warp(v, Wih1_s, w.gi1, w.bi1, w.bh1, w.go1, w.bo1,
                     gates_s[warp], lane);

    float p = act ? hval * w.Wout[lane] : 0.f;
    p = warp_sum(p);
    if (lane == 0) {
        float val = p + w.bout[0];
        __half hv = __float2half_rn(val);
        __half* H = reinterpret_cast<__half*>(g_tab_h2);
        H[2 * entry] = hv;                       // pair[entry].x
        if (entry > 0) H[2 * entry - 1] = hv;    // pair[entry-1].y
        if (entry == TAB_N - 1) H[2 * entry + 1] = hv;  // defined, never read
    }
}

// ===================== kernel 2: replicated smem table linear interp ========
// tab4[4*i + r] = g_tab_h2[i] for r = 0..3; lane l reads copy (l & 3).
__device__ __forceinline__ float interp_one_s(float xx, unsigned rep,
                                              const unsigned int* __restrict__ tab4) {
    float t = __saturatef(fmaf(xx, TAB_A, TAB_B)) * TAB_T_MAX;  // FFMA.SAT+FMUL
    int i = __float2int_rd(t);
    float s = t - (float)i;
    unsigned int u = tab4[((unsigned)i << 2) | rep];  // one LDS.32, class-banked
    __half2 h = *reinterpret_cast<const __half2*>(&u);
    float2 q = __half22float2(h);                 // {F[i], F[i+1]}
    return fmaf(s, q.y - q.x, q.x);
}

#define ITHREADS 128   // 1954 blocks -> ~13 CTAs/SM
#define VPT 4          // float4s per thread, blocked addressing

__global__ void __launch_bounds__(ITHREADS)
interp_kernel(const float4* __restrict__ x4, float4* __restrict__ o4, int n4,
              const float* __restrict__ x, float* __restrict__ out, int n) {
    __shared__ unsigned int tab_s[4 * TAB_N];    // 16KB, 4-way interleaved

    // stage + replicate: each thread expands 2 source uint4s into 8 splat uint4s
    {
        const uint4* src = (const uint4*)g_tab_h2;   // TAB_N/4 = 256 uint4
        uint4* dst = (uint4*)tab_s;                  // dst[i] = splat(word i)
#pragma unroll
        for (int j = 0; j < TAB_N / 4 / ITHREADS; j++) {
            int t = threadIdx.x + j * ITHREADS;
            uint4 v = src[t];
            dst[4 * t + 0] = make_uint4(v.x, v.x, v.x, v.x);
            dst[4 * t + 1] = make_uint4(v.y, v.y, v.y, v.y);
            dst[4 * t + 2] = make_uint4(v.z, v.z, v.z, v.z);
            dst[4 * t + 3] = make_uint4(v.w, v.w, v.w, v.w);
        }
    }
    __syncthreads();

    const unsigned rep = threadIdx.x & 3;
    int base = blockIdx.x * (ITHREADS * VPT) + threadIdx.x;

    if (base + (VPT - 1) * ITHREADS < n4) {      // hot: full block, no guards
        float4 xv[VPT];
#pragma unroll
        for (int j = 0; j < VPT; j++) xv[j] = __ldcs(&x4[base + j * ITHREADS]);
#pragma unroll
        for (int j = 0; j < VPT; j++) {
            float4 ov;
            ov.x = interp_one_s(xv[j].x, rep, tab_s);
            ov.y = interp_one_s(xv[j].y, rep, tab_s);
            ov.z = interp_one_s(xv[j].z, rep, tab_s);
            ov.w = interp_one_s(xv[j].w, rep, tab_s);
            __stcs(&o4[base + j * ITHREADS], ov);
        }
    } else {                                      // edge block
#pragma unroll
        for (int j = 0; j < VPT; j++) {
            int idx = base + j * ITHREADS;
            if (idx < n4) {
                float4 xv = __ldcs(&x4[idx]);
                float4 ov;
                ov.x = interp_one_s(xv.x, rep, tab_s);
                ov.y = interp_one_s(xv.y, rep, tab_s);
                ov.z = interp_one_s(xv.z, rep, tab_s);
                ov.w = interp_one_s(xv.w, rep, tab_s);
                __stcs(&o4[idx], ov);
            }
        }
        // n % 4 tail
        if (blockIdx.x == gridDim.x - 1 && threadIdx.x < 32) {
            for (int i = n4 * 4 + threadIdx.x; i < n; i += 32)
                out[i] = interp_one_s(x[i], rep, tab_s);
        }
    }
}

extern "C" void kernel_launch(void* const* d_in, const int* in_sizes, int n_in,
                              void* d_out, int out_size) {
    Weights w;
    w.W1 = (const float*)d_in[1];
    w.b1 = (const float*)d_in[2];
    w.g1 = (const float*)d_in[3];
    w.be1 = (const float*)d_in[4];
    w.Wih0 = (const float*)d_in[5];
    w.gi0 = (const float*)d_in[7];
    w.bi0 = (const float*)d_in[8];
    w.bh0 = (const float*)d_in[10];
    w.go0 = (const float*)d_in[11];
    w.bo0 = (const float*)d_in[12];
    w.Wih1 = (const float*)d_in[13];
    w.gi1 = (const float*)d_in[15];
    w.bi1 = (const float*)d_in[16];
    w.bh1 = (const float*)d_in[18];
    w.go1 = (const float*)d_in[19];
    w.bo1 = (const float*)d_in[20];
    w.Wout = (const float*)d_in[21];
    w.bout = (const float*)d_in[22];

    const float* x = (const float*)d_in[0];
    float* out = (float*)d_out;
    int n = in_sizes[0];
    int n4 = n / 4;

    build_table_kernel<<<TAB_N / BUILD_WARPS, 32 * BUILD_WARPS>>>(w);

    int per_block = ITHREADS * VPT;
    int blocks = (n4 + per_block - 1) / per_block;
    if (blocks == 0) blocks = 1;
    interp_kernel<<<blocks, ITHREADS>>>((const float4*)x, (float4*)out, n4,
                                        x, out, n);
}